// round 15
// baseline (speedup 1.0000x reference)
// rev: R15 — fp16 hi-plane gather aggregation (halved traffic); bnfin inlined
#include <cuda_runtime.h>
#include <cuda_fp16.h>
#include <cstdint>

#define NMAX 50000
#define EMAX 800000
#define NPAD 50048   // multiple of 32

// ---------------------------------------------------------------------------
// Scratch (static __device__ arrays — no allocation allowed)
// ---------------------------------------------------------------------------
__device__ int    g_count[NMAX];
__device__ int    g_rowptr[NMAX + 1];
__device__ int    g_cursor[NMAX];
__device__ int    g_esrc[EMAX];
// Pre-split fp16 hi/lo A-operand planes (disjoint per layout):
// bufA (stride 208): [x 0..99 | zero 100..103 | mean(x) 104..207]
// bufB (stride 256): [mean(h1) 0..127 | h1 128..255]
// bufC (stride 128): [h2] then [bnrelu(t1)]
__device__ __half g_a1hi[(size_t)NPAD * 208], g_a1lo[(size_t)NPAD * 208];
__device__ __half g_a2hi[(size_t)NPAD * 256], g_a2lo[(size_t)NPAD * 256];
__device__ __half g_a3hi[(size_t)NPAD * 128], g_a3lo[(size_t)NPAD * 128];
__device__ float  g_t1[(size_t)NMAX * 128];   // pre-BN MLP1 activations
__device__ float  g_t2[(size_t)NMAX * 64];    // pre-BN MLP2 activations
__device__ float  g_s1[128], g_q1[128], g_s2[64], g_q2[64];   // BN sums / sumsq

// ---------------------------------------------------------------------------
// fp16 split helpers (Markidis split: v = hi + lo)
// ---------------------------------------------------------------------------
__device__ __forceinline__ void split2(float v0, float v1, uint32_t& hi, uint32_t& lo) {
    __half2 h = __floats2half2_rn(v0, v1);
    float2 hf = __half22float2(h);
    __half2 l = __floats2half2_rn(v0 - hf.x, v1 - hf.y);
    hi = *(uint32_t*)&h;
    lo = *(uint32_t*)&l;
}
__device__ __forceinline__ void split_store(__half* hi_p, __half* lo_p,
                                            float v0, float v1) {
    uint32_t hi, lo;
    split2(v0, v1, hi, lo);
    *(uint32_t*)hi_p = hi;
    *(uint32_t*)lo_p = lo;
}
__device__ __forceinline__ uint32_t sm_u32(const void* p) {
    return (uint32_t)__cvta_generic_to_shared(p);
}
__device__ __forceinline__ void ldsm_x4(uint32_t& r0, uint32_t& r1,
                                        uint32_t& r2, uint32_t& r3, uint32_t addr) {
    asm volatile("ldmatrix.sync.aligned.m8n8.x4.shared.b16 {%0,%1,%2,%3}, [%4];"
                 : "=r"(r0), "=r"(r1), "=r"(r2), "=r"(r3) : "r"(addr));
}
__device__ __forceinline__ void mma_f16(float* c,
                                        uint32_t a0, uint32_t a1, uint32_t a2, uint32_t a3,
                                        uint32_t b0, uint32_t b1) {
    asm volatile(
        "mma.sync.aligned.m16n8k16.row.col.f32.f16.f16.f32 "
        "{%0,%1,%2,%3}, {%4,%5,%6,%7}, {%8,%9}, {%0,%1,%2,%3};"
        : "+f"(c[0]), "+f"(c[1]), "+f"(c[2]), "+f"(c[3])
        : "r"(a0), "r"(a1), "r"(a2), "r"(a3), "r"(b0), "r"(b1));
}
__device__ __forceinline__ void cp16(uint32_t smem, const void* g) {
    asm volatile("cp.async.cg.shared.global [%0], [%1], 16;" :: "r"(smem), "l"(g) : "memory");
}
__device__ __forceinline__ void cpcommit() {
    asm volatile("cp.async.commit_group;" ::: "memory");
}
template <int NW>
__device__ __forceinline__ void cpwait() {
    asm volatile("cp.async.wait_group %0;" :: "n"(NW) : "memory");
}
// accumulate 8 halves (uint4) into 8 fp32 accumulators
__device__ __forceinline__ void acc8(float* a, uint4 u) {
    const __half2* h = (const __half2*)&u;
#pragma unroll
    for (int j = 0; j < 4; j++) {
        float2 f = __half22float2(h[j]);
        a[2 * j]     += f.x;
        a[2 * j + 1] += f.y;
    }
}

// ---------------------------------------------------------------------------
// CSR build: zero -> histogram -> scan -> scatter
// ---------------------------------------------------------------------------
__global__ void k_zero(int n) {
    int i = blockIdx.x * blockDim.x + threadIdx.x;
    if (i < n) g_count[i] = 0;
    if (i < 128) { g_s1[i] = 0.f; g_q1[i] = 0.f; }
    if (i < 64)  { g_s2[i] = 0.f; g_q2[i] = 0.f; }
}

__global__ void k_hist(const int* __restrict__ dst, int E) {
    int i = blockIdx.x * blockDim.x + threadIdx.x;
    if (i < E) atomicAdd(&g_count[dst[i]], 1);
}

__global__ void k_scan(int N) {
    __shared__ int sums[1024];
    int t = threadIdx.x;
    int chunk = (N + 1023) >> 10;
    int b = t * chunk;
    int e = b + chunk; if (e > N) e = N;
    int s = 0;
    for (int i = b; i < e; i++) s += g_count[i];
    sums[t] = s;
    __syncthreads();
    int own = s;
    for (int off = 1; off < 1024; off <<= 1) {
        int v = (t >= off) ? sums[t - off] : 0;
        __syncthreads();
        sums[t] += v;
        __syncthreads();
    }
    int pre = sums[t] - own;  // exclusive prefix
    for (int i = b; i < e; i++) {
        g_rowptr[i] = pre;
        g_cursor[i] = pre;
        pre += g_count[i];
    }
    if (t == 1023) g_rowptr[N] = sums[1023];
}

__global__ void k_scatter(const int* __restrict__ src, const int* __restrict__ dst, int E) {
    int i = blockIdx.x * blockDim.x + threadIdx.x;
    if (i < E) {
        int d = dst[i];
        int p = atomicAdd(&g_cursor[d], 1);
        g_esrc[p] = src[i];
    }
}

// ---------------------------------------------------------------------------
// Split passes
// ---------------------------------------------------------------------------
// x -> bufA cols [0,104) stride 208 (cols 100..103 zeroed)
__global__ void k_splitx(const float* __restrict__ x,
                         __half* __restrict__ hi, __half* __restrict__ lo, int N) {
    int i = blockIdx.x * blockDim.x + threadIdx.x;
    int r = i / 52, k2 = i % 52;
    if (r >= N) return;
    float v0 = 0.f, v1 = 0.f;
    if (k2 < 50) {
        float2 v = *(const float2*)&x[(size_t)r * 100 + 2 * k2];
        v0 = v.x; v1 = v.y;
    }
    size_t off = (size_t)r * 208 + 2 * k2;
    split_store(&hi[off], &lo[off], v0, v1);
}

// bn-relu(t1) -> bufC (stride 128); alpha/beta computed per block from stats
__global__ void k_splitbn(const float* __restrict__ src,
                          const float* __restrict__ s, const float* __restrict__ q,
                          const float* __restrict__ gam, const float* __restrict__ bet,
                          __half* __restrict__ hi, __half* __restrict__ lo,
                          float invN, int N) {
    __shared__ float sal[128], sbt[128];
    if (threadIdx.x < 128) {
        float m = s[threadIdx.x] * invN;
        float v = q[threadIdx.x] * invN - m * m;
        float a = gam[threadIdx.x] * rsqrtf(v + 1e-5f);
        sal[threadIdx.x] = a;
        sbt[threadIdx.x] = bet[threadIdx.x] - m * a;
    }
    __syncthreads();
    int i = blockIdx.x * blockDim.x + threadIdx.x;
    int r = i / 64, k2 = i % 64;
    if (r >= N) return;
    int k = 2 * k2;
    float2 v = *(const float2*)&src[(size_t)r * 128 + k];
    float v0 = fmaxf(fmaf(v.x, sal[k], sbt[k]), 0.f);
    float v1 = fmaxf(fmaf(v.y, sal[k + 1], sbt[k + 1]), 0.f);
    size_t off = (size_t)r * 128 + k;
    split_store(&hi[off], &lo[off], v0, v1);
}

// ---------------------------------------------------------------------------
// Mean aggregation, fp16 hi-plane gather: warp per node, lane = 8-col group.
// Reads neighbor rows from the hi plane (half traffic of fp32), accumulates
// fp32, writes mean as split hi/lo at cols [DSTOFF, DSTOFF + NG*8).
// ---------------------------------------------------------------------------
template <int NG, int KP, int SRCOFF, int DSTOFF>
__global__ void k_aggregate(const __half* __restrict__ ahi,
                            __half* __restrict__ mhi, __half* __restrict__ mlo, int N) {
    int g = blockIdx.x * blockDim.x + threadIdx.x;
    int w = g >> 5;
    int lane = g & 31;
    if (w >= N) return;
    int s = g_rowptr[w], e = g_rowptr[w + 1];
    bool act = (lane < NG);
    int col = SRCOFF + lane * 8;
    float a[8];
#pragma unroll
    for (int j = 0; j < 8; j++) a[j] = 0.f;
    int i = s;
    for (; i + 3 < e; i += 4) {
        int s0 = g_esrc[i], s1 = g_esrc[i + 1], s2 = g_esrc[i + 2], s3 = g_esrc[i + 3];
        if (act) {
            uint4 u0 = *(const uint4*)&ahi[(size_t)s0 * KP + col];
            uint4 u1 = *(const uint4*)&ahi[(size_t)s1 * KP + col];
            uint4 u2 = *(const uint4*)&ahi[(size_t)s2 * KP + col];
            uint4 u3 = *(const uint4*)&ahi[(size_t)s3 * KP + col];
            acc8(a, u0); acc8(a, u1); acc8(a, u2); acc8(a, u3);
        }
    }
    for (; i < e; i++) {
        int s0 = g_esrc[i];
        if (act) {
            uint4 u = *(const uint4*)&ahi[(size_t)s0 * KP + col];
            acc8(a, u);
        }
    }
    if (act) {
        float inv = (e > s) ? 1.f / (float)(e - s) : 0.f;  // deg=0 -> mean=0
        uint4 h, l;
        split2(a[0] * inv, a[1] * inv, h.x, l.x);
        split2(a[2] * inv, a[3] * inv, h.y, l.y);
        split2(a[4] * inv, a[5] * inv, h.z, l.z);
        split2(a[6] * inv, a[7] * inv, h.w, l.w);
        size_t off = (size_t)w * KP + DSTOFF + lane * 8;   // 16B aligned
        *(uint4*)&mhi[off] = h;
        *(uint4*)&mlo[off] = l;
    }
}

// ---------------------------------------------------------------------------
// Fused tensor-core GEMM, split-FP16, pre-split A, cp.async double-buffered:
//   out[N, COLS] = epi( A @ W + bias ),  W rows: [0,KWA)=Wa, [KOFFB,KOFFB+KWB)=Wb,
//   zero elsewhere (matches bufA/bufB column layouts).
//   EPI 1 (RELU): relu store; optional split hi/lo plane write (Shi/Slo)
//   EPI 2 (STATS): raw store + per-column sum/sumsq accumulation
// ---------------------------------------------------------------------------
template <int KP, int KWA, int KOFFB, int KWB, int COLS, int EPI>
__global__ void __launch_bounds__(256)
k_gemm(const __half* __restrict__ Ahi, const __half* __restrict__ Alo,
       const float* __restrict__ Wa, const float* __restrict__ Wb,
       const float* __restrict__ bias,
       float* __restrict__ outp,
       float* __restrict__ statS, float* __restrict__ statQ,
       __half* __restrict__ Shi, __half* __restrict__ Slo, int SKP, int SOFF,
       int N) {
    constexpr int KP2  = KP / 2;
    constexpr int SAh  = ((KP - 8 + 63) / 64) * 64 + 8; // %64 == 8
    constexpr int BM   = 32;
    constexpr int CHUNK = KP / 8;
    constexpr int CG   = (COLS == 128) ? 8 : 4;
    constexpr int RG   = 8 / CG;
    constexpr int MT   = 2 / RG;
    constexpr int WCOLS = COLS / CG;                     // 16
    constexpr int NT   = WCOLS / 8;                      // 2
    constexpr int KSTEPS = KP / 16;

    extern __shared__ __half sm_h[];
    __half* Wt_hi = sm_h;                    // [COLS][SAh]
    __half* Wt_lo = Wt_hi + COLS * SAh;
    __half* As    = Wt_lo + COLS * SAh;      // [2 stages][2 planes][BM][SAh]
    constexpr int STAGE = 2 * BM * SAh;

    int tid = threadIdx.x;
    int lane = tid & 31, wid = tid >> 5;
    int wc, wr;
    if (RG == 1) { wc = wid; wr = 0; }
    else         { wc = wid >> 1; wr = wid & 1; }
    int rowbase = wr * 16 * MT;
    int gid = lane >> 2, tig = lane & 3;

    // Stage W once (transposed [col][k], hi/lo split, KOFFB placement).
    for (int i = tid; i < COLS * KP2; i += 256) {
        int k2 = i / COLS, c = i % COLS;
        int k = k2 * 2;
        float v0 = 0.f, v1 = 0.f;
        if (k < KWA) {
            v0 = Wa[k * COLS + c];
            v1 = Wa[(k + 1) * COLS + c];
        } else if (KWB > 0 && k >= KOFFB && k < KOFFB + KWB) {
            v0 = Wb[(k - KOFFB) * COLS + c];
            v1 = Wb[(k - KOFFB + 1) * COLS + c];
        }
        split_store(Wt_hi + c * SAh + k, Wt_lo + c * SAh + k, v0, v1);
    }

    uint32_t aOff[MT];
#pragma unroll
    for (int mt = 0; mt < MT; mt++) {
        int row = rowbase + mt * 16 + (lane & 15);
        aOff[mt] = sm_u32(As + row * SAh + (lane >> 4) * 8);
    }
    uint32_t bHi, bLo;
    {
        int col = wc * WCOLS + ((lane >> 4) & 1) * 8 + (lane & 7);
        int off = col * SAh + ((lane >> 3) & 1) * 8;
        bHi = sm_u32(Wt_hi + off);
        bLo = sm_u32(Wt_lo + off);
    }

    float bs0[NT], bs1[NT];
#pragma unroll
    for (int nt = 0; nt < NT; nt++) {
        int c = wc * WCOLS + nt * 8 + 2 * tig;
        bs0[nt] = bias[c];
        bs1[nt] = bias[c + 1];
    }

    float sS[NT * 2], sQ[NT * 2];
#pragma unroll
    for (int j = 0; j < NT * 2; j++) { sS[j] = 0.f; sQ[j] = 0.f; }

    int ntiles = (N + BM - 1) / BM;
    int nloc = ((int)blockIdx.x < ntiles)
                   ? (ntiles - (int)blockIdx.x + (int)gridDim.x - 1) / (int)gridDim.x : 0;

    auto prefetch = [&](int li, int stage) {
        int t0 = ((int)blockIdx.x + li * (int)gridDim.x) * BM;
        __half* dstp = As + stage * STAGE;
        for (int j = tid; j < 2 * BM * CHUNK; j += 256) {
            int plane = (j >= BM * CHUNK) ? 1 : 0;
            int rem = j - plane * BM * CHUNK;
            int r = rem / CHUNK, c8 = (rem % CHUNK) * 8;
            const __half* g = (plane ? Alo : Ahi) + (size_t)(t0 + r) * KP + c8;
            cp16(sm_u32(dstp + plane * BM * SAh + r * SAh + c8), g);
        }
    };

    if (nloc > 0) { prefetch(0, 0); }
    cpcommit();

    for (int li = 0; li < nloc; li++) {
        int t0 = ((int)blockIdx.x + li * (int)gridDim.x) * BM;
        bool more = (li + 1 < nloc);
        if (more) { prefetch(li + 1, (li + 1) & 1); cpcommit(); }
        if (more) cpwait<1>(); else cpwait<0>();
        __syncthreads();

        uint32_t stageB = (uint32_t)((li & 1) * STAGE * 2);

        float acc[MT][NT][4];
#pragma unroll
        for (int mt = 0; mt < MT; mt++)
#pragma unroll
            for (int nt = 0; nt < NT; nt++)
#pragma unroll
                for (int j = 0; j < 4; j++) acc[mt][nt][j] = 0.f;

#pragma unroll 2
        for (int k0 = 0; k0 < KSTEPS * 16; k0 += 16) {
            uint32_t kb = k0 * 2;
            uint32_t ah[MT][4], al[MT][4];
#pragma unroll
            for (int mt = 0; mt < MT; mt++) {
                ldsm_x4(ah[mt][0], ah[mt][1], ah[mt][2], ah[mt][3],
                        aOff[mt] + stageB + kb);
                ldsm_x4(al[mt][0], al[mt][1], al[mt][2], al[mt][3],
                        aOff[mt] + stageB + (uint32_t)(BM * SAh * 2) + kb);
            }
            uint32_t bh[NT][2], bl[NT][2];
            ldsm_x4(bh[0][0], bh[0][1], bh[1][0], bh[1][1], bHi + kb);
            ldsm_x4(bl[0][0], bl[0][1], bl[1][0], bl[1][1], bLo + kb);
#pragma unroll
            for (int nt = 0; nt < NT; nt++) {
#pragma unroll
                for (int mt = 0; mt < MT; mt++) {
                    mma_f16(acc[mt][nt], al[mt][0], al[mt][1], al[mt][2], al[mt][3],
                            bh[nt][0], bh[nt][1]);
                    mma_f16(acc[mt][nt], ah[mt][0], ah[mt][1], ah[mt][2], ah[mt][3],
                            bl[nt][0], bl[nt][1]);
                    mma_f16(acc[mt][nt], ah[mt][0], ah[mt][1], ah[mt][2], ah[mt][3],
                            bh[nt][0], bh[nt][1]);
                }
            }
        }

        // Epilogue
#pragma unroll
        for (int mt = 0; mt < MT; mt++) {
            int r0 = t0 + rowbase + mt * 16 + gid;
            int r1 = r0 + 8;
#pragma unroll
            for (int nt = 0; nt < NT; nt++) {
                int col = wc * WCOLS + nt * 8 + 2 * tig;
                float o0 = acc[mt][nt][0] + bs0[nt];
                float o1 = acc[mt][nt][1] + bs1[nt];
                float o2 = acc[mt][nt][2] + bs0[nt];
                float o3 = acc[mt][nt][3] + bs1[nt];
                if (EPI == 1) {
                    o0 = fmaxf(o0, 0.f); o1 = fmaxf(o1, 0.f);
                    o2 = fmaxf(o2, 0.f); o3 = fmaxf(o3, 0.f);
                }
                if (r0 < N) {
                    if (EPI == 2) {
                        sS[nt * 2]     += o0; sQ[nt * 2]     += o0 * o0;
                        sS[nt * 2 + 1] += o1; sQ[nt * 2 + 1] += o1 * o1;
                    }
                    *(float2*)&outp[(size_t)r0 * COLS + col] = make_float2(o0, o1);
                    if (EPI == 1 && SKP) {
                        size_t so = (size_t)r0 * SKP + SOFF + col;
                        uint32_t h, l;
                        split2(o0, o1, h, l);
                        *(uint32_t*)&Shi[so] = h;
                        *(uint32_t*)&Slo[so] = l;
                    }
                }
                if (r1 < N) {
                    if (EPI == 2) {
                        sS[nt * 2]     += o2; sQ[nt * 2]     += o2 * o2;
                        sS[nt * 2 + 1] += o3; sQ[nt * 2 + 1] += o3 * o3;
                    }
                    *(float2*)&outp[(size_t)r1 * COLS + col] = make_float2(o2, o3);
                    if (EPI == 1 && SKP) {
                        size_t so = (size_t)r1 * SKP + SOFF + col;
                        uint32_t h, l;
                        split2(o2, o3, h, l);
                        *(uint32_t*)&Shi[so] = h;
                        *(uint32_t*)&Slo[so] = l;
                    }
                }
            }
        }
        __syncthreads();
    }

    if (EPI == 2) {
#pragma unroll
        for (int j = 0; j < NT * 2; j++) {
            float s = sS[j], q = sQ[j];
#pragma unroll
            for (int o = 4; o < 32; o <<= 1) {
                s += __shfl_xor_sync(0xffffffffu, s, o);
                q += __shfl_xor_sync(0xffffffffu, q, o);
            }
            if (gid == 0) {
                int col = wc * WCOLS + (j >> 1) * 8 + 2 * tig + (j & 1);
                atomicAdd(&statS[col], s);
                atomicAdd(&statQ[col], q);
            }
        }
    }
}

// ---------------------------------------------------------------------------
// Final head: out[i] = relu(BN2(t2[i])) . W3 + b3 (warp per node);
// BN2 alpha/beta computed per block from stats (bnfin inlined).
// ---------------------------------------------------------------------------
__global__ void k_final(const float* __restrict__ W3, const float* __restrict__ b3,
                        const float* __restrict__ s, const float* __restrict__ q,
                        const float* __restrict__ gam, const float* __restrict__ bet,
                        float invN, float* __restrict__ out, int N) {
    __shared__ float sal[64], sbt[64];
    if (threadIdx.x < 64) {
        float m = s[threadIdx.x] * invN;
        float v = q[threadIdx.x] * invN - m * m;
        float a = gam[threadIdx.x] * rsqrtf(v + 1e-5f);
        sal[threadIdx.x] = a;
        sbt[threadIdx.x] = bet[threadIdx.x] - m * a;
    }
    __syncthreads();
    int g = blockIdx.x * blockDim.x + threadIdx.x;
    int w = g >> 5;
    int lane = g & 31;
    if (w >= N) return;
    float ta = g_t2[(size_t)w * 64 + lane];
    float tb = g_t2[(size_t)w * 64 + 32 + lane];
    float za = fmaxf(ta * sal[lane] + sbt[lane], 0.f);
    float zb = fmaxf(tb * sal[lane + 32] + sbt[lane + 32], 0.f);
    float p = za * W3[lane] + zb * W3[lane + 32];
#pragma unroll
    for (int o = 16; o > 0; o >>= 1) p += __shfl_xor_sync(0xffffffffu, p, o);
    if (lane == 0) out[w] = p + b3[0];
}

// ---------------------------------------------------------------------------
// Host launcher
// ---------------------------------------------------------------------------
extern "C" void kernel_launch(void* const* d_in, const int* in_sizes, int n_in,
                              void* d_out, int out_size) {
    const float* x   = (const float*)d_in[0];
    const int*   ei  = (const int*)d_in[1];
    const float* Wl1 = (const float*)d_in[2];
    const float* bl1 = (const float*)d_in[3];
    const float* Wr1 = (const float*)d_in[4];
    const float* Wl2 = (const float*)d_in[5];
    const float* bl2 = (const float*)d_in[6];
    const float* Wr2 = (const float*)d_in[7];
    const float* W1  = (const float*)d_in[8];
    const float* b1  = (const float*)d_in[9];
    const float* g1  = (const float*)d_in[10];
    const float* be1 = (const float*)d_in[11];
    const float* W2  = (const float*)d_in[12];
    const float* b2  = (const float*)d_in[13];
    const float* g2  = (const float*)d_in[14];
    const float* be2 = (const float*)d_in[15];
    const float* W3  = (const float*)d_in[16];
    const float* b3  = (const float*)d_in[17];

    int N = in_sizes[0] / 100;
    int E = in_sizes[1] / 2;
    const int* src = ei;
    const int* dst = ei + E;

    float* out = (float*)d_out;
    float* h1  = out + N;
    float* h2  = h1 + (size_t)N * 128;

    __half *a1h, *a1l, *a2h, *a2l, *a3h, *a3l;
    float *p_t1, *p_t2, *p_s1, *p_q1, *p_s2, *p_q2;
    cudaGetSymbolAddress((void**)&a1h, g_a1hi);
    cudaGetSymbolAddress((void**)&a1l, g_a1lo);
    cudaGetSymbolAddress((void**)&a2h, g_a2hi);
    cudaGetSymbolAddress((void**)&a2l, g_a2lo);
    cudaGetSymbolAddress((void**)&a3h, g_a3hi);
    cudaGetSymbolAddress((void**)&a3l, g_a3lo);
    cudaGetSymbolAddress((void**)&p_t1, g_t1);
    cudaGetSymbolAddress((void**)&p_t2, g_t2);
    cudaGetSymbolAddress((void**)&p_s1, g_s1);
    cudaGetSymbolAddress((void**)&p_q1, g_q1);
    cudaGetSymbolAddress((void**)&p_s2, g_s2);
    cudaGetSymbolAddress((void**)&p_q2, g_q2);

    const int SM_SAGE = (2 * 128 * 264 + 4 * 32 * 264) * 2;  // 202752
    const int SM_M1   = (2 * 128 * 136 + 4 * 32 * 136) * 2;  // 104448
    const int SM_M2   = (2 * 64 * 136 + 4 * 32 * 136) * 2;   //  69632

    cudaFuncSetAttribute(k_gemm<208, 100, 104, 100, 128, 1>,
                         cudaFuncAttributeMaxDynamicSharedMemorySize, SM_SAGE);
    cudaFuncSetAttribute(k_gemm<256, 128, 128, 128, 128, 1>,
                         cudaFuncAttributeMaxDynamicSharedMemorySize, SM_SAGE);
    cudaFuncSetAttribute(k_gemm<128, 128, 128, 0, 128, 2>,
                         cudaFuncAttributeMaxDynamicSharedMemorySize, SM_M1);
    cudaFuncSetAttribute(k_gemm<128, 128, 128, 0, 64, 2>,
                         cudaFuncAttributeMaxDynamicSharedMemorySize, SM_M2);

    float invN = 1.f / (float)N;

    // --- CSR build (once; reused by both SAGE layers) ---
    k_zero<<<(N + 255) / 256, 256>>>(N);
    k_hist<<<(E + 255) / 256, 256>>>(dst, E);
    k_scan<<<1, 1024>>>(N);
    k_scatter<<<(E + 255) / 256, 256>>>(src, dst, E);

    // --- SAGE layer 1: h1 = relu([x | mean(x)] @ [Wr1 ; Wl1] + bl1) ---
    k_splitx<<<(N * 52 + 255) / 256, 256>>>(x, a1h, a1l, N);   // x -> bufA[0..103]
    k_aggregate<13, 208, 0, 104><<<(N + 7) / 8, 256>>>(a1h, a1h, a1l, N);
    k_gemm<208, 100, 104, 100, 128, 1><<<148, 256, SM_SAGE>>>(
        a1h, a1l, Wr1, Wl1, bl1, h1, nullptr, nullptr,
        a2h, a2l, 256, 128, N);                                // fused h1->bufB[128..255]

    // --- SAGE layer 2: h2 = relu([mean(h1) | h1] @ [Wl2 ; Wr2] + bl2) ---
    k_aggregate<16, 256, 128, 0><<<(N + 7) / 8, 256>>>(a2h, a2h, a2l, N);
    k_gemm<256, 128, 128, 128, 128, 1><<<148, 256, SM_SAGE>>>(
        a2h, a2l, Wl2, Wr2, bl2, h2, nullptr, nullptr,
        a3h, a3l, 128, 0, N);                                  // fused h2->bufC

    // --- MLP layer 1 (pre-BN t1 + column stats) ---
    k_gemm<128, 128, 128, 0, 128, 2><<<296, 256, SM_M1>>>(
        a3h, a3l, W1, nullptr, b1, p_t1, p_s1, p_q1,
        nullptr, nullptr, 0, 0, N);

    // --- MLP layer 2 (BN1 inlined in split pass; pre-BN t2 + stats) ---
    k_splitbn<<<(N * 64 + 255) / 256, 256>>>(p_t1, p_s1, p_q1, g1, be1,
                                             a3h, a3l, invN, N);
    k_gemm<128, 128, 128, 0, 64, 2><<<444, 256, SM_M2>>>(
        a3h, a3l, W2, nullptr, b2, p_t2, p_s2, p_q2,
        nullptr, nullptr, 0, 0, N);

    // --- Head: BN2 (inlined) + relu + dot ---
    k_final<<<(N + 7) / 8, 256>>>(W3, b3, p_s2, p_q2, g2, be2, invN, out, N);
}

// round 16
// speedup vs baseline: 1.0645x; 1.0645x over previous
// rev: R16 — revert to fp32 gather (R14); add PDL (programmatic dependent launch)
#include <cuda_runtime.h>
#include <cuda_fp16.h>
#include <cstdint>

#define NMAX 50000
#define EMAX 800000
#define NPAD 50048   // multiple of 32

// ---------------------------------------------------------------------------
// Scratch (static __device__ arrays — no allocation allowed)
// ---------------------------------------------------------------------------
__device__ int    g_count[NMAX];
__device__ int    g_rowptr[NMAX + 1];
__device__ int    g_cursor[NMAX];
__device__ int    g_esrc[EMAX];
// Pre-split fp16 hi/lo A-operand planes (disjoint per layout):
// bufA (stride 208): [mean(x) 0..99 | x 100..199 | zero 200..207]
// bufB (stride 256): [mean(h1) 0..127 | h1 128..255]
// bufC (stride 128): [h2] then [bnrelu(t1)]
__device__ __half g_a1hi[(size_t)NPAD * 208], g_a1lo[(size_t)NPAD * 208];
__device__ __half g_a2hi[(size_t)NPAD * 256], g_a2lo[(size_t)NPAD * 256];
__device__ __half g_a3hi[(size_t)NPAD * 128], g_a3lo[(size_t)NPAD * 128];
__device__ float  g_t1[(size_t)NMAX * 128];   // pre-BN MLP1 activations
__device__ float  g_t2[(size_t)NMAX * 64];    // pre-BN MLP2 activations
__device__ float  g_s1[128], g_q1[128], g_s2[64], g_q2[64];   // BN sums / sumsq

// ---------------------------------------------------------------------------
// PDL: consumer-side wait (producers trigger implicitly at completion)
// ---------------------------------------------------------------------------
#define GDC_WAIT() asm volatile("griddepcontrol.wait;" ::: "memory")

// ---------------------------------------------------------------------------
// fp16 split helpers (Markidis split: v = hi + lo)
// ---------------------------------------------------------------------------
__device__ __forceinline__ void split2(float v0, float v1, uint32_t& hi, uint32_t& lo) {
    __half2 h = __floats2half2_rn(v0, v1);
    float2 hf = __half22float2(h);
    __half2 l = __floats2half2_rn(v0 - hf.x, v1 - hf.y);
    hi = *(uint32_t*)&h;
    lo = *(uint32_t*)&l;
}
__device__ __forceinline__ void split_store(__half* hi_p, __half* lo_p,
                                            float v0, float v1) {
    uint32_t hi, lo;
    split2(v0, v1, hi, lo);
    *(uint32_t*)hi_p = hi;
    *(uint32_t*)lo_p = lo;
}
__device__ __forceinline__ uint32_t sm_u32(const void* p) {
    return (uint32_t)__cvta_generic_to_shared(p);
}
__device__ __forceinline__ void ldsm_x4(uint32_t& r0, uint32_t& r1,
                                        uint32_t& r2, uint32_t& r3, uint32_t addr) {
    asm volatile("ldmatrix.sync.aligned.m8n8.x4.shared.b16 {%0,%1,%2,%3}, [%4];"
                 : "=r"(r0), "=r"(r1), "=r"(r2), "=r"(r3) : "r"(addr));
}
__device__ __forceinline__ void mma_f16(float* c,
                                        uint32_t a0, uint32_t a1, uint32_t a2, uint32_t a3,
                                        uint32_t b0, uint32_t b1) {
    asm volatile(
        "mma.sync.aligned.m16n8k16.row.col.f32.f16.f16.f32 "
        "{%0,%1,%2,%3}, {%4,%5,%6,%7}, {%8,%9}, {%0,%1,%2,%3};"
        : "+f"(c[0]), "+f"(c[1]), "+f"(c[2]), "+f"(c[3])
        : "r"(a0), "r"(a1), "r"(a2), "r"(a3), "r"(b0), "r"(b1));
}
__device__ __forceinline__ void cp16(uint32_t smem, const void* g) {
    asm volatile("cp.async.cg.shared.global [%0], [%1], 16;" :: "r"(smem), "l"(g) : "memory");
}
__device__ __forceinline__ void cpcommit() {
    asm volatile("cp.async.commit_group;" ::: "memory");
}
template <int NW>
__device__ __forceinline__ void cpwait() {
    asm volatile("cp.async.wait_group %0;" :: "n"(NW) : "memory");
}

// ---------------------------------------------------------------------------
// CSR build: zero -> histogram -> scan -> scatter
// ---------------------------------------------------------------------------
__global__ void k_zero(int n) {
    int i = blockIdx.x * blockDim.x + threadIdx.x;
    if (i < n) g_count[i] = 0;
    if (i < 128) { g_s1[i] = 0.f; g_q1[i] = 0.f; }
    if (i < 64)  { g_s2[i] = 0.f; g_q2[i] = 0.f; }
}

__global__ void k_hist(const int* __restrict__ dst, int E) {
    GDC_WAIT();
    int i = blockIdx.x * blockDim.x + threadIdx.x;
    if (i < E) atomicAdd(&g_count[dst[i]], 1);
}

__global__ void k_scan(int N) {
    GDC_WAIT();
    __shared__ int sums[1024];
    int t = threadIdx.x;
    int chunk = (N + 1023) >> 10;
    int b = t * chunk;
    int e = b + chunk; if (e > N) e = N;
    int s = 0;
    for (int i = b; i < e; i++) s += g_count[i];
    sums[t] = s;
    __syncthreads();
    int own = s;
    for (int off = 1; off < 1024; off <<= 1) {
        int v = (t >= off) ? sums[t - off] : 0;
        __syncthreads();
        sums[t] += v;
        __syncthreads();
    }
    int pre = sums[t] - own;  // exclusive prefix
    for (int i = b; i < e; i++) {
        g_rowptr[i] = pre;
        g_cursor[i] = pre;
        pre += g_count[i];
    }
    if (t == 1023) g_rowptr[N] = sums[1023];
}

__global__ void k_scatter(const int* __restrict__ src, const int* __restrict__ dst, int E) {
    GDC_WAIT();
    int i = blockIdx.x * blockDim.x + threadIdx.x;
    if (i < E) {
        int d = dst[i];
        int p = atomicAdd(&g_cursor[d], 1);
        g_esrc[p] = src[i];
    }
}

// ---------------------------------------------------------------------------
// Split passes
// ---------------------------------------------------------------------------
// x -> bufA cols [100,208) stride 208 (cols 200..207 zeroed every launch)
__global__ void k_splitx(const float* __restrict__ x,
                         __half* __restrict__ hi, __half* __restrict__ lo, int N) {
    GDC_WAIT();
    int i = blockIdx.x * blockDim.x + threadIdx.x;
    int r = i / 54, k2 = i % 54;
    if (r >= N) return;
    float v0 = 0.f, v1 = 0.f;
    if (k2 < 50) {
        float2 v = *(const float2*)&x[(size_t)r * 100 + 2 * k2];
        v0 = v.x; v1 = v.y;
    }
    size_t off = (size_t)r * 208 + 100 + 2 * k2;
    split_store(&hi[off], &lo[off], v0, v1);
}

// bn-relu(t1) -> bufC (stride 128); alpha/beta computed per block from stats
__global__ void k_splitbn(const float* __restrict__ src,
                          const float* __restrict__ s, const float* __restrict__ q,
                          const float* __restrict__ gam, const float* __restrict__ bet,
                          __half* __restrict__ hi, __half* __restrict__ lo,
                          float invN, int N) {
    GDC_WAIT();
    __shared__ float sal[128], sbt[128];
    if (threadIdx.x < 128) {
        float m = s[threadIdx.x] * invN;
        float v = q[threadIdx.x] * invN - m * m;
        float a = gam[threadIdx.x] * rsqrtf(v + 1e-5f);
        sal[threadIdx.x] = a;
        sbt[threadIdx.x] = bet[threadIdx.x] - m * a;
    }
    __syncthreads();
    int i = blockIdx.x * blockDim.x + threadIdx.x;
    int r = i / 64, k2 = i % 64;
    if (r >= N) return;
    int k = 2 * k2;
    float2 v = *(const float2*)&src[(size_t)r * 128 + k];
    float v0 = fmaxf(fmaf(v.x, sal[k], sbt[k]), 0.f);
    float v1 = fmaxf(fmaf(v.y, sal[k + 1], sbt[k + 1]), 0.f);
    size_t off = (size_t)r * 128 + k;
    split_store(&hi[off], &lo[off], v0, v1);
}

// ---------------------------------------------------------------------------
// Mean aggregation (fp32 gather): warp per node, CSR gather, x4 unroll;
// epilogue writes the mean directly as split hi/lo planes at cols [0,F).
// ---------------------------------------------------------------------------
template <int F, int KP>
__global__ void k_aggregate(const float* __restrict__ feat,
                            __half* __restrict__ mhi, __half* __restrict__ mlo, int N) {
    GDC_WAIT();
    int g = blockIdx.x * blockDim.x + threadIdx.x;
    int w = g >> 5;
    int lane = g & 31;
    if (w >= N) return;
    int s = g_rowptr[w], e = g_rowptr[w + 1];
    constexpr int Q = F / 4;
    bool act = (lane < Q);
    int col = lane * 4;
    float ax = 0.f, ay = 0.f, az = 0.f, aw = 0.f;
    int i = s;
    for (; i + 3 < e; i += 4) {
        int s0 = g_esrc[i], s1 = g_esrc[i + 1], s2 = g_esrc[i + 2], s3 = g_esrc[i + 3];
        if (act) {
            float4 v0 = *(const float4*)&feat[(size_t)s0 * F + col];
            float4 v1 = *(const float4*)&feat[(size_t)s1 * F + col];
            float4 v2 = *(const float4*)&feat[(size_t)s2 * F + col];
            float4 v3 = *(const float4*)&feat[(size_t)s3 * F + col];
            ax += v0.x + v1.x + v2.x + v3.x;
            ay += v0.y + v1.y + v2.y + v3.y;
            az += v0.z + v1.z + v2.z + v3.z;
            aw += v0.w + v1.w + v2.w + v3.w;
        }
    }
    for (; i < e; i++) {
        int s0 = g_esrc[i];
        if (act) {
            float4 v = *(const float4*)&feat[(size_t)s0 * F + col];
            ax += v.x; ay += v.y; az += v.z; aw += v.w;
        }
    }
    if (act) {
        float inv = (e > s) ? 1.f / (float)(e - s) : 0.f;  // deg=0 -> mean=0
        uint32_t h0, l0, h1, l1;
        split2(ax * inv, ay * inv, h0, l0);
        split2(az * inv, aw * inv, h1, l1);
        size_t off = (size_t)w * KP + col;   // 8B aligned
        *(uint2*)&mhi[off] = make_uint2(h0, h1);
        *(uint2*)&mlo[off] = make_uint2(l0, l1);
    }
}

// ---------------------------------------------------------------------------
// Fused tensor-core GEMM, split-FP16, pre-split A, cp.async double-buffered:
//   out[N, COLS] = epi( A @ [Wa ; Wb] + bias )   W rows [0,KWA)=Wa, [KWA,KWA+KWB)=Wb
//   EPI 1 (RELU): relu store; optional split hi/lo plane write (Shi/Slo)
//   EPI 2 (STATS): raw store + per-column sum/sumsq accumulation
// ---------------------------------------------------------------------------
template <int KP, int KWA, int KWB, int COLS, int EPI>
__global__ void __launch_bounds__(256)
k_gemm(const __half* __restrict__ Ahi, const __half* __restrict__ Alo,
       const float* __restrict__ Wa, const float* __restrict__ Wb,
       const float* __restrict__ bias,
       float* __restrict__ outp,
       float* __restrict__ statS, float* __restrict__ statQ,
       __half* __restrict__ Shi, __half* __restrict__ Slo, int SKP, int SOFF,
       int N) {
    constexpr int K    = KWA + KWB;
    constexpr int KP2  = KP / 2;
    constexpr int SAh  = ((KP - 8 + 63) / 64) * 64 + 8; // %64 == 8
    constexpr int BM   = 32;
    constexpr int CHUNK = KP / 8;
    constexpr int CG   = (COLS == 128) ? 8 : 4;
    constexpr int RG   = 8 / CG;
    constexpr int MT   = 2 / RG;
    constexpr int WCOLS = COLS / CG;                     // 16
    constexpr int NT   = WCOLS / 8;                      // 2
    constexpr int KSTEPS = KP / 16;

    extern __shared__ __half sm_h[];
    __half* Wt_hi = sm_h;                    // [COLS][SAh]
    __half* Wt_lo = Wt_hi + COLS * SAh;
    __half* As    = Wt_lo + COLS * SAh;      // [2 stages][2 planes][BM][SAh]
    constexpr int STAGE = 2 * BM * SAh;

    GDC_WAIT();

    int tid = threadIdx.x;
    int lane = tid & 31, wid = tid >> 5;
    int wc, wr;
    if (RG == 1) { wc = wid; wr = 0; }
    else         { wc = wid >> 1; wr = wid & 1; }
    int rowbase = wr * 16 * MT;
    int gid = lane >> 2, tig = lane & 3;

    // Stage W once (transposed [col][k], hi/lo split). Coalesced over columns.
    for (int i = tid; i < COLS * KP2; i += 256) {
        int k2 = i / COLS, c = i % COLS;
        int k = k2 * 2;
        float v0 = 0.f, v1 = 0.f;
        if (k < KWA) {
            v0 = Wa[k * COLS + c];
            v1 = Wa[(k + 1) * COLS + c];
        } else if (KWB > 0 && k < K) {
            v0 = Wb[(k - KWA) * COLS + c];
            v1 = Wb[(k - KWA + 1) * COLS + c];
        }
        split_store(Wt_hi + c * SAh + k, Wt_lo + c * SAh + k, v0, v1);
    }

    uint32_t aOff[MT];
#pragma unroll
    for (int mt = 0; mt < MT; mt++) {
        int row = rowbase + mt * 16 + (lane & 15);
        aOff[mt] = sm_u32(As + row * SAh + (lane >> 4) * 8);
    }
    uint32_t bHi, bLo;
    {
        int col = wc * WCOLS + ((lane >> 4) & 1) * 8 + (lane & 7);
        int off = col * SAh + ((lane >> 3) & 1) * 8;
        bHi = sm_u32(Wt_hi + off);
        bLo = sm_u32(Wt_lo + off);
    }

    float bs0[NT], bs1[NT];
#pragma unroll
    for (int nt = 0; nt < NT; nt++) {
        int c = wc * WCOLS + nt * 8 + 2 * tig;
        bs0[nt] = bias[c];
        bs1[nt] = bias[c + 1];
    }

    float sS[NT * 2], sQ[NT * 2];
#pragma unroll
    for (int j = 0; j < NT * 2; j++) { sS[j] = 0.f; sQ[j] = 0.f; }

    int ntiles = (N + BM - 1) / BM;
    int nloc = ((int)blockIdx.x < ntiles)
                   ? (ntiles - (int)blockIdx.x + (int)gridDim.x - 1) / (int)gridDim.x : 0;

    auto prefetch = [&](int li, int stage) {
        int t0 = ((int)blockIdx.x + li * (int)gridDim.x) * BM;
        __half* dstp = As + stage * STAGE;
        for (int j = tid; j < 2 * BM * CHUNK; j += 256) {
            int plane = (j >= BM * CHUNK) ? 1 : 0;
            int rem = j - plane * BM * CHUNK;
            int r = rem / CHUNK, c8 = (rem % CHUNK) * 8;
            const __half* g = (plane ? Alo : Ahi) + (size_t)(t0 + r) * KP + c8;
            cp16(sm_u32(dstp + plane * BM * SAh + r * SAh + c8), g);
        }
    };

    if (nloc > 0) { prefetch(0, 0); }
    cpcommit();

    for (int li = 0; li < nloc; li++) {
        int t0 = ((int)blockIdx.x + li * (int)gridDim.x) * BM;
        bool more = (li + 1 < nloc);
        if (more) { prefetch(li + 1, (li + 1) & 1); cpcommit(); }
        if (more) cpwait<1>(); else cpwait<0>();
        __syncthreads();

        uint32_t stageB = (uint32_t)((li & 1) * STAGE * 2);

        float acc[MT][NT][4];
#pragma unroll
        for (int mt = 0; mt < MT; mt++)
#pragma unroll
            for (int nt = 0; nt < NT; nt++)
#pragma unroll
                for (int j = 0; j < 4; j++) acc[mt][nt][j] = 0.f;

#pragma unroll 2
        for (int k0 = 0; k0 < KSTEPS * 16; k0 += 16) {
            uint32_t kb = k0 * 2;
            uint32_t ah[MT][4], al[MT][4];
#pragma unroll
            for (int mt = 0; mt < MT; mt++) {
                ldsm_x4(ah[mt][0], ah[mt][1], ah[mt][2], ah[mt][3],
                        aOff[mt] + stageB + kb);
                ldsm_x4(al[mt][0], al[mt][1], al[mt][2], al[mt][3],
                        aOff[mt] + stageB + (uint32_t)(BM * SAh * 2) + kb);
            }
            uint32_t bh[NT][2], bl[NT][2];
            ldsm_x4(bh[0][0], bh[0][1], bh[1][0], bh[1][1], bHi + kb);
            ldsm_x4(bl[0][0], bl[0][1], bl[1][0], bl[1][1], bLo + kb);
#pragma unroll
            for (int nt = 0; nt < NT; nt++) {
#pragma unroll
                for (int mt = 0; mt < MT; mt++) {
                    mma_f16(acc[mt][nt], al[mt][0], al[mt][1], al[mt][2], al[mt][3],
                            bh[nt][0], bh[nt][1]);
                    mma_f16(acc[mt][nt], ah[mt][0], ah[mt][1], ah[mt][2], ah[mt][3],
                            bl[nt][0], bl[nt][1]);
                    mma_f16(acc[mt][nt], ah[mt][0], ah[mt][1], ah[mt][2], ah[mt][3],
                            bh[nt][0], bh[nt][1]);
                }
            }
        }

        // Epilogue
#pragma unroll
        for (int mt = 0; mt < MT; mt++) {
            int r0 = t0 + rowbase + mt * 16 + gid;
            int r1 = r0 + 8;
#pragma unroll
            for (int nt = 0; nt < NT; nt++) {
                int col = wc * WCOLS + nt * 8 + 2 * tig;
                float o0 = acc[mt][nt][0] + bs0[nt];
                float o1 = acc[mt][nt][1] + bs1[nt];
                float o2 = acc[mt][nt][2] + bs0[nt];
                float o3 = acc[mt][nt][3] + bs1[nt];
                if (EPI == 1) {
                    o0 = fmaxf(o0, 0.f); o1 = fmaxf(o1, 0.f);
                    o2 = fmaxf(o2, 0.f); o3 = fmaxf(o3, 0.f);
                }
                if (r0 < N) {
                    if (EPI == 2) {
                        sS[nt * 2]     += o0; sQ[nt * 2]     += o0 * o0;
                        sS[nt * 2 + 1] += o1; sQ[nt * 2 + 1] += o1 * o1;
                    }
                    *(float2*)&outp[(size_t)r0 * COLS + col] = make_float2(o0, o1);
                    if (EPI == 1 && SKP) {
                        size_t so = (size_t)r0 * SKP + SOFF + col;
                        uint32_t h, l;
                        split2(o0, o1, h, l);
                        *(uint32_t*)&Shi[so] = h;
                        *(uint32_t*)&Slo[so] = l;
                    }
                }
                if (r1 < N) {
                    if (EPI == 2) {
                        sS[nt * 2]     += o2; sQ[nt * 2]     += o2 * o2;
                        sS[nt * 2 + 1] += o3; sQ[nt * 2 + 1] += o3 * o3;
                    }
                    *(float2*)&outp[(size_t)r1 * COLS + col] = make_float2(o2, o3);
                    if (EPI == 1 && SKP) {
                        size_t so = (size_t)r1 * SKP + SOFF + col;
                        uint32_t h, l;
                        split2(o2, o3, h, l);
                        *(uint32_t*)&Shi[so] = h;
                        *(uint32_t*)&Slo[so] = l;
                    }
                }
            }
        }
        __syncthreads();
    }

    if (EPI == 2) {
#pragma unroll
        for (int j = 0; j < NT * 2; j++) {
            float s = sS[j], q = sQ[j];
#pragma unroll
            for (int o = 4; o < 32; o <<= 1) {
                s += __shfl_xor_sync(0xffffffffu, s, o);
                q += __shfl_xor_sync(0xffffffffu, q, o);
            }
            if (gid == 0) {
                int col = wc * WCOLS + (j >> 1) * 8 + 2 * tig + (j & 1);
                atomicAdd(&statS[col], s);
                atomicAdd(&statQ[col], q);
            }
        }
    }
}

// ---------------------------------------------------------------------------
// Final head: out[i] = relu(BN2(t2[i])) . W3 + b3 (warp per node);
// BN2 alpha/beta computed per block from stats (bnfin inlined).
// ---------------------------------------------------------------------------
__global__ void k_final(const float* __restrict__ W3, const float* __restrict__ b3,
                        const float* __restrict__ s, const float* __restrict__ q,
                        const float* __restrict__ gam, const float* __restrict__ bet,
                        float invN, float* __restrict__ out, int N) {
    GDC_WAIT();
    __shared__ float sal[64], sbt[64];
    if (threadIdx.x < 64) {
        float m = s[threadIdx.x] * invN;
        float v = q[threadIdx.x] * invN - m * m;
        float a = gam[threadIdx.x] * rsqrtf(v + 1e-5f);
        sal[threadIdx.x] = a;
        sbt[threadIdx.x] = bet[threadIdx.x] - m * a;
    }
    __syncthreads();
    int g = blockIdx.x * blockDim.x + threadIdx.x;
    int w = g >> 5;
    int lane = g & 31;
    if (w >= N) return;
    float ta = g_t2[(size_t)w * 64 + lane];
    float tb = g_t2[(size_t)w * 64 + 32 + lane];
    float za = fmaxf(ta * sal[lane] + sbt[lane], 0.f);
    float zb = fmaxf(tb * sal[lane + 32] + sbt[lane + 32], 0.f);
    float p = za * W3[lane] + zb * W3[lane + 32];
#pragma unroll
    for (int o = 16; o > 0; o >>= 1) p += __shfl_xor_sync(0xffffffffu, p, o);
    if (lane == 0) out[w] = p + b3[0];
}

// ---------------------------------------------------------------------------
// Host: PDL launch helper (secondary launch overlaps predecessor's execution)
// ---------------------------------------------------------------------------
template <typename F, typename... Args>
static inline void launch_pdl(F f, dim3 grid, dim3 block, size_t smem, Args... args) {
    cudaLaunchConfig_t cfg = {};
    cfg.gridDim = grid;
    cfg.blockDim = block;
    cfg.dynamicSmemBytes = smem;
    cfg.stream = 0;   // legacy default stream (same as <<<>>>, captured by harness)
    cudaLaunchAttribute attr[1];
    attr[0].id = cudaLaunchAttributeProgrammaticStreamSerialization;
    attr[0].val.programmaticStreamSerializationAllowed = 1;
    cfg.attrs = attr;
    cfg.numAttrs = 1;
    cudaLaunchKernelEx(&cfg, f, args...);
}

extern "C" void kernel_launch(void* const* d_in, const int* in_sizes, int n_in,
                              void* d_out, int out_size) {
    const float* x   = (const float*)d_in[0];
    const int*   ei  = (const int*)d_in[1];
    const float* Wl1 = (const float*)d_in[2];
    const float* bl1 = (const float*)d_in[3];
    const float* Wr1 = (const float*)d_in[4];
    const float* Wl2 = (const float*)d_in[5];
    const float* bl2 = (const float*)d_in[6];
    const float* Wr2 = (const float*)d_in[7];
    const float* W1  = (const float*)d_in[8];
    const float* b1  = (const float*)d_in[9];
    const float* g1  = (const float*)d_in[10];
    const float* be1 = (const float*)d_in[11];
    const float* W2  = (const float*)d_in[12];
    const float* b2  = (const float*)d_in[13];
    const float* g2  = (const float*)d_in[14];
    const float* be2 = (const float*)d_in[15];
    const float* W3  = (const float*)d_in[16];
    const float* b3  = (const float*)d_in[17];

    int N = in_sizes[0] / 100;
    int E = in_sizes[1] / 2;
    const int* src = ei;
    const int* dst = ei + E;

    float* out = (float*)d_out;
    float* h1  = out + N;
    float* h2  = h1 + (size_t)N * 128;

    __half *a1h, *a1l, *a2h, *a2l, *a3h, *a3l;
    float *p_t1, *p_t2, *p_s1, *p_q1, *p_s2, *p_q2;
    cudaGetSymbolAddress((void**)&a1h, g_a1hi);
    cudaGetSymbolAddress((void**)&a1l, g_a1lo);
    cudaGetSymbolAddress((void**)&a2h, g_a2hi);
    cudaGetSymbolAddress((void**)&a2l, g_a2lo);
    cudaGetSymbolAddress((void**)&a3h, g_a3hi);
    cudaGetSymbolAddress((void**)&a3l, g_a3lo);
    cudaGetSymbolAddress((void**)&p_t1, g_t1);
    cudaGetSymbolAddress((void**)&p_t2, g_t2);
    cudaGetSymbolAddress((void**)&p_s1, g_s1);
    cudaGetSymbolAddress((void**)&p_q1, g_q1);
    cudaGetSymbolAddress((void**)&p_s2, g_s2);
    cudaGetSymbolAddress((void**)&p_q2, g_q2);

    const int SM_SAGE = (2 * 128 * 264 + 4 * 32 * 264) * 2;  // 202752
    const int SM_M1   = (2 * 128 * 136 + 4 * 32 * 136) * 2;  // 104448
    const int SM_M2   = (2 * 64 * 136 + 4 * 32 * 136) * 2;   //  69632

    cudaFuncSetAttribute(k_gemm<208, 100, 100, 128, 1>,
                         cudaFuncAttributeMaxDynamicSharedMemorySize, SM_SAGE);
    cudaFuncSetAttribute(k_gemm<256, 128, 128, 128, 1>,
                         cudaFuncAttributeMaxDynamicSharedMemorySize, SM_SAGE);
    cudaFuncSetAttribute(k_gemm<128, 128, 0, 128, 2>,
                         cudaFuncAttributeMaxDynamicSharedMemorySize, SM_M1);
    cudaFuncSetAttribute(k_gemm<128, 128, 0, 64, 2>,
                         cudaFuncAttributeMaxDynamicSharedMemorySize, SM_M2);

    float invN = 1.f / (float)N;

    // --- CSR build (once; reused by both SAGE layers) ---
    launch_pdl(k_zero, dim3((N + 255) / 256), dim3(256), 0, N);
    launch_pdl(k_hist, dim3((E + 255) / 256), dim3(256), 0, dst, E);
    launch_pdl(k_scan, dim3(1), dim3(1024), 0, N);
    launch_pdl(k_scatter, dim3((E + 255) / 256), dim3(256), 0, src, dst, E);

    // --- SAGE layer 1: h1 = relu([mean(x) | x] @ [Wl1 ; Wr1] + bl1) ---
    launch_pdl(k_splitx, dim3((N * 54 + 255) / 256), dim3(256), 0, x, a1h, a1l, N);
    launch_pdl(k_aggregate<100, 208>, dim3((N + 7) / 8), dim3(256), 0,
               x, a1h, a1l, N);
    launch_pdl(k_gemm<208, 100, 100, 128, 1>, dim3(148), dim3(256), (size_t)SM_SAGE,
               (const __half*)a1h, (const __half*)a1l, Wl1, Wr1, bl1, h1,
               (float*)nullptr, (float*)nullptr, a2h, a2l, 256, 128, N);

    // --- SAGE layer 2: h2 = relu([mean(h1) | h1] @ [Wl2 ; Wr2] + bl2) ---
    launch_pdl(k_aggregate<128, 256>, dim3((N + 7) / 8), dim3(256), 0,
               (const float*)h1, a2h, a2l, N);
    launch_pdl(k_gemm<256, 128, 128, 128, 1>, dim3(148), dim3(256), (size_t)SM_SAGE,
               (const __half*)a2h, (const __half*)a2l, Wl2, Wr2, bl2, h2,
               (float*)nullptr, (float*)nullptr, a3h, a3l, 128, 0, N);

    // --- MLP layer 1 (pre-BN t1 + column stats) ---
    launch_pdl(k_gemm<128, 128, 0, 128, 2>, dim3(296), dim3(256), (size_t)SM_M1,
               (const __half*)a3h, (const __half*)a3l, W1, (const float*)nullptr, b1,
               p_t1, p_s1, p_q1, (__half*)nullptr, (__half*)nullptr, 0, 0, N);

    // --- MLP layer 2 (BN1 inlined in split pass; pre-BN t2 + stats) ---
    launch_pdl(k_splitbn, dim3((N * 64 + 255) / 256), dim3(256), 0,
               (const float*)p_t1, (const float*)p_s1, (const float*)p_q1, g1, be1,
               a3h, a3l, invN, N);
    launch_pdl(k_gemm<128, 128, 0, 64, 2>, dim3(444), dim3(256), (size_t)SM_M2,
               (const __half*)a3h, (const __half*)a3l, W2, (const float*)nullptr, b2,
               p_t2, p_s2, p_q2, (__half*)nullptr, (__half*)nullptr, 0, 0, N);

    // --- Head: BN2 (inlined) + relu + dot ---
    launch_pdl(k_final, dim3((N + 7) / 8), dim3(256), 0,
               W3, b3, (const float*)p_s2, (const float*)p_q2, g2, be2, invN, out, N);
}